// round 15
// baseline (speedup 1.0000x reference)
#include <cuda_runtime.h>
#include <math.h>
#include <stdint.h>

#define T_TOK 8192
#define CDIM  1024
#define HDIM  4096
#define NEXP  8
#define TM    128
#define TNB   128                            // CTA tile N
#define MAXTILES 136
#define HROWS_MAX (MAXTILES * TM)
#define NSTAGE 3
#define KSTG   32
#define A_STG_BYTES (TM * KSTG * 4)          // 16384 (two 8KB k16 sub-buffers)
#define B_STG_BYTES (TNB * KSTG * 4)         // 16384

// ---------------- device scratch ----------------
__device__ int   g_cnt[NEXP];
__device__ int   g_off[NEXP];
__device__ int   g_tok[NEXP * T_TOK];
__device__ float g_wt [NEXP * T_TOK];
__device__ int   g_tile_e[MAXTILES];
__device__ int   g_tile_l[MAXTILES];
__device__ int   g_ntiles;
__device__ int   g_done;
// A-side buffers PACKED per 16-row group, k16-block major:
//   quad(p, wp) = {A[r][2wp], A[r+8][2wp], A[r][2wp+1], A[r+8][2wp+1]}, r = grp*16+p
//   quad index  = (wp>>3)*64 + p*8 + (wp&7)   (float offset = idx*4)
__device__ float g_X[(size_t)HROWS_MAX * CDIM];      // gathered x, packed, tf32-rounded
__device__ float g_H[(size_t)HROWS_MAX * HDIM];      // activations, packed, tf32-rounded
__device__ float g_W1[(size_t)NEXP * HDIM * CDIM];   // tf32-rounded weights (linear)
__device__ float g_W2[(size_t)NEXP * CDIM * HDIM];

// ---------------- helpers ----------------
__device__ __forceinline__ unsigned int f2tf32(float f) {
    unsigned int r;
    asm("cvt.rna.tf32.f32 %0, %1;" : "=r"(r) : "f"(f));
    return r;
}
__device__ __forceinline__ float rna_tf32(float f) { return __uint_as_float(f2tf32(f)); }

__device__ __forceinline__ uint32_t smem_u32(const void* p) {
    uint32_t a;
    asm("{ .reg .u64 t; cvta.to.shared.u64 t, %1; cvt.u32.u64 %0, t; }" : "=r"(a) : "l"(p));
    return a;
}
__device__ __forceinline__ void cpasync16(uint32_t dst, const float* src) {
    asm volatile("cp.async.cg.shared.global [%0], [%1], 16;" :: "r"(dst), "l"(src));
}
#define CP_COMMIT()  asm volatile("cp.async.commit_group;" ::: "memory")
#define CP_WAIT(n)   asm volatile("cp.async.wait_group %0;" :: "n"(n) : "memory")

__device__ __forceinline__ void mma_tf32(float c[4], unsigned int a0, unsigned int a1,
                                         unsigned int a2, unsigned int a3,
                                         unsigned int b0, unsigned int b1) {
    asm volatile(
        "mma.sync.aligned.m16n8k8.row.col.f32.tf32.tf32.f32 "
        "{%0,%1,%2,%3}, {%4,%5,%6,%7}, {%8,%9}, {%0,%1,%2,%3};"
        : "+f"(c[0]), "+f"(c[1]), "+f"(c[2]), "+f"(c[3])
        : "r"(a0), "r"(a1), "r"(a2), "r"(a3), "r"(b0), "r"(b1));
}

__device__ __forceinline__ float gelu_tanh(float v) {
    float u = v + 0.044715f * v * v * v;
    return 0.5f * v * (1.0f + tanhf(0.7978845608028654f * u));
}

// ---------------- weight conversion (+ counter resets), one kernel ----------------
__global__ void convw_all(const float* __restrict__ w1, const float* __restrict__ w2) {
    if (blockIdx.x == 0) {
        if (threadIdx.x < NEXP) g_cnt[threadIdx.x] = 0;
        if (threadIdx.x == NEXP) g_done = 0;
    }
    const size_t half = (size_t)(NEXP * HDIM * CDIM) / 4;   // float4 count per weight
    size_t i = (size_t)blockIdx.x * 256 + threadIdx.x;
    const float4* src;
    float4* dst;
    if (i < half) { src = (const float4*)w1; dst = (float4*)g_W1; }
    else          { src = (const float4*)w2; dst = (float4*)g_W2; i -= half; }
    float4 v = src[i];
    v.x = rna_tf32(v.x); v.y = rna_tf32(v.y); v.z = rna_tf32(v.z); v.w = rna_tf32(v.w);
    dst[i] = v;
}

// ---------------- router (+ fused scheduler via completion counter) ----------------
__global__ void router_kernel(const float* __restrict__ x,
                              const float* __restrict__ gw) {
    __shared__ float xs[CDIM];
    __shared__ float lg[NEXP];
    const int t = blockIdx.x, tid = threadIdx.x;
    ((float4*)xs)[tid] = ((const float4*)(x + (size_t)t * CDIM))[tid];
    __syncthreads();
    const int e = tid >> 5, lane = tid & 31;
    const float* w = gw + e * CDIM;
    float s = 0.f;
    for (int i = lane * 4; i < CDIM; i += 128) {
        float4 a = *(const float4*)(xs + i);
        float4 b = *(const float4*)(w + i);
        s += a.x * b.x + a.y * b.y + a.z * b.z + a.w * b.w;
    }
    #pragma unroll
    for (int o = 16; o; o >>= 1) s += __shfl_xor_sync(0xffffffffu, s, o);
    if (lane == 0) lg[e] = s;
    __syncthreads();
    if (tid == 0) {
        float m = lg[0];
        #pragma unroll
        for (int i = 1; i < NEXP; i++) m = fmaxf(m, lg[i]);
        float p[NEXP]; float S = 0.f;
        #pragma unroll
        for (int i = 0; i < NEXP; i++) { p[i] = expf(lg[i] - m); S += p[i]; }
        #pragma unroll
        for (int i = 0; i < NEXP; i++) p[i] /= S;
        int i1 = 0;
        #pragma unroll
        for (int i = 1; i < NEXP; i++) if (p[i] > p[i1]) i1 = i;
        int i2 = (i1 == 0) ? 1 : 0;
        #pragma unroll
        for (int i = 0; i < NEXP; i++) { if (i == i1) continue; if (p[i] > p[i2]) i2 = i; }
        float denom = p[i1] + p[i2] + 1e-8f;
        float wa = p[i1] / denom, wb = p[i2] / denom;
        int pos = atomicAdd(&g_cnt[i1], 1);
        g_tok[i1 * T_TOK + pos] = t; g_wt[i1 * T_TOK + pos] = wa;
        pos = atomicAdd(&g_cnt[i2], 1);
        g_tok[i2 * T_TOK + pos] = t; g_wt[i2 * T_TOK + pos] = wb;

        __threadfence();
        int old = atomicAdd(&g_done, 1);
        if (old == T_TOK - 1) {
            int acc = 0, nt = 0;
            for (int ee = 0; ee < NEXP; ee++) {
                g_off[ee] = acc;
                int c = g_cnt[ee];
                int k = (c + TM - 1) / TM;
                for (int i = 0; i < k; i++) { g_tile_e[nt] = ee; g_tile_l[nt] = i; nt++; }
                acc += k * TM;
            }
            g_ntiles = nt;
            __threadfence();
        }
    }
}

// gather + rna-round x rows into PACKED per-expert segments (zero padding).
__global__ void gather_kernel(const float* __restrict__ x) {
    const int grp  = blockIdx.x;
    const int tile = grp >> 3;
    if (tile >= g_ntiles) return;
    const int e    = g_tile_e[tile];
    const int cnt  = g_cnt[e];
    const int t    = threadIdx.x;
    const int p    = t >> 5, c = t & 31;
    const int lr0  = g_tile_l[tile] * TM + (grp & 7) * 16 + p;
    const int lr8  = lr0 + 8;
    const float* s0 = (lr0 < cnt) ? x + (size_t)g_tok[e * T_TOK + lr0] * CDIM : nullptr;
    const float* s8 = (lr8 < cnt) ? x + (size_t)g_tok[e * T_TOK + lr8] * CDIM : nullptr;
    float4* dst = (float4*)(g_X + (size_t)grp * 16 * CDIM);
    #pragma unroll
    for (int j = 0; j < CDIM / 64; j++) {      // 16 iters
        const int wp = c + 32 * j;
        float2 a = s0 ? *(const float2*)(s0 + 2 * wp) : make_float2(0.f, 0.f);
        float2 b = s8 ? *(const float2*)(s8 + 2 * wp) : make_float2(0.f, 0.f);
        float4 v;
        v.x = rna_tf32(a.x); v.y = rna_tf32(b.x);
        v.z = rna_tf32(a.y); v.w = rna_tf32(b.y);
        dst[((c >> 3) + 4 * j) * 64 + p * 8 + (c & 7)] = v;
    }
}

// ---------------- grouped GEMM, mma.sync tf32, cp.async pipeline ----------------
// CTA tile 128x128, 4 warps as 2(m) x 2(n), warp tile 64x64. 2 CTAs/SM.
// Packed-A (one LDS.128 = one in-order HMMA quad). Full-XOR smem swizzle.
// Pipeline: wait(1) -> sync -> MMA(sub0) -> PRODUCE -> MMA(sub1).
// FFN2 grid is (n-tile FAST, m-tile slow): a wave covers all 8 n-tiles of
// ~37 m-tiles -> each g_H slab read from DRAM once, L2-hits for the rest
// (g_H = 285MB > L2, so tile-fast order would re-stream it every wave).
// MMA order within j: all k0 (distinct acc) then all k1 -> RAW distance 4.
#define FFN_SMEM (1024 + NSTAGE * (A_STG_BYTES + B_STG_BYTES))

template <int KDIM, bool FFN1>
__global__ void __launch_bounds__(128, 2) ffn_gemm(const float* __restrict__ bias,
                                                   float* __restrict__ outp) {
    extern __shared__ char smem[];
    const int tile = FFN1 ? blockIdx.x : blockIdx.y;
    const int nblk = FFN1 ? blockIdx.y : blockIdx.x;
    if (tile >= g_ntiles) return;

    const float* Aglb = FFN1 ? g_X  : g_H;    // packed A (device-side symbol refs)
    const float* Bglb = FFN1 ? g_W1 : g_W2;

    const int e     = g_tile_e[tile];
    const int l     = g_tile_l[tile];
    const int cnt   = g_cnt[e];
    const int r0    = l * TM;
    const int valid = min(TM, cnt - r0);
    const int NB    = FFN1 ? HDIM : CDIM;
    const int n0    = nblk * TNB;
    const float* Bexp = Bglb + (size_t)e * KDIM * NB;
    const float* be   = bias + e * NB;
    const int hbase   = g_off[e] + r0;        // multiple of 128
    const int tid = threadIdx.x, wid = tid >> 5, lane = tid & 31;

    int*   tok_s = (int*)smem;
    float* wt_s  = (float*)(smem + 512);
    unsigned int* Asm = (unsigned int*)(smem + 1024);
    unsigned int* Bsm = (unsigned int*)(smem + 1024 + NSTAGE * A_STG_BYTES);
    const uint32_t Abase_u = smem_u32(Asm);
    const uint32_t Bbase_u = smem_u32(Bsm);

    {   // all 128 threads load token map
        bool v = tid < valid;
        int idx = e * T_TOK + r0 + tid;
        tok_s[tid] = v ? g_tok[idx] : 0;
        wt_s[tid]  = v ? g_wt[idx]  : 0.f;
    }
    __syncthreads();

    // cp.async mapping for one 32-k stage (A chunk c: q fast -> coalesced src):
    const float* aS[8]; uint32_t aD[8];
    const float* bS[8]; uint32_t bD[8];
    #pragma unroll
    for (int i = 0; i < 8; i++) {
        const int c = tid + 128 * i;
        const int q = c & 7, p = (c >> 3) & 7, grp = (c >> 6) & 7, sub = c >> 9;
        aS[i] = Aglb + ((size_t)((hbase >> 4) + grp)) * (16 * KDIM) + sub * 256 + p * 32 + q * 4;
        aD[i] = Abase_u + sub * (A_STG_BYTES / 2) + grp * 1024 + (p * 8 + (q ^ p)) * 16;
        const int row = c >> 3, cw = c & 7;
        bS[i] = Bexp + (size_t)(n0 + row) * KDIM + cw * 4;
        bD[i] = Bbase_u + (cw >> 2) * (B_STG_BYTES / 2) + row * 64 + (cw & 3) * 16;
    }

    #define PRODUCE(bufi, kof) do { \
        const uint32_t _oa = (bufi) * A_STG_BYTES; \
        const uint32_t _ob = (bufi) * B_STG_BYTES; \
        _Pragma("unroll") \
        for (int _i = 0; _i < 8; _i++) cpasync16(aD[_i] + _oa, aS[_i] + ((kof) << 4)); \
        _Pragma("unroll") \
        for (int _i = 0; _i < 8; _i++) cpasync16(bD[_i] + _ob, bS[_i] + (kof)); \
        CP_COMMIT(); \
    } while (0)

    const int wm = (wid & 1) * 64;        // warp m offset (0/64)
    const int wn = (wid >> 1) * 64;       // warp n offset (0/64)
    const int g  = lane >> 2, tg = lane & 3;
    const int aoff0 = (g * 8 + ((2 * tg)     ^ g)) * 4;
    const int aoff1 = (g * 8 + ((2 * tg + 1) ^ g)) * 4;

    float acc[4][8][4];
    #pragma unroll
    for (int i = 0; i < 4; i++)
        #pragma unroll
        for (int j = 0; j < 8; j++)
            #pragma unroll
            for (int q = 0; q < 4; q++) acc[i][j][q] = 0.f;

    // within each j: 4 independent k0-mmas then 4 independent k1-mmas
    // (RAW distance on acc[i][j] = 4 instructions; no extra register cost)
    #define MMA_SUB(Ab, Bb) do { \
        uint4 aQ[4][2]; \
        _Pragma("unroll") \
        for (int i = 0; i < 4; i++) { \
            const int gb = ((wm >> 4) + i) * 256; \
            aQ[i][0] = *(const uint4*)((Ab) + gb + aoff0); \
            aQ[i][1] = *(const uint4*)((Ab) + gb + aoff1); \
        } \
        _Pragma("unroll") \
        for (int j = 0; j < 8; j++) { \
            const int nb = wn + j * 8 + g; \
            const uint4 bF = *(const uint4*)((Bb) + nb * 16 + tg * 4); \
            _Pragma("unroll") \
            for (int i = 0; i < 4; i++) \
                mma_tf32(acc[i][j], aQ[i][0].x, aQ[i][0].y, aQ[i][0].z, aQ[i][0].w, \
                         bF.x, bF.y); \
            _Pragma("unroll") \
            for (int i = 0; i < 4; i++) \
                mma_tf32(acc[i][j], aQ[i][1].x, aQ[i][1].y, aQ[i][1].z, aQ[i][1].w, \
                         bF.z, bF.w); \
        } \
    } while (0)

    const int NSTG = KDIM / KSTG;         // 32 (FFN1) or 128 (FFN2)
    PRODUCE(0, 0);
    PRODUCE(1, KSTG);

    int bufc = 0, bufp = 2;
    #pragma unroll 1
    for (int s = 0; s < NSTG; s++) {
        CP_WAIT(1);                       // commits = 2+s; complete >= s+1
        __syncthreads();                  // single barrier per stage

        const unsigned int* AbS = Asm + bufc * (A_STG_BYTES / 4);
        const unsigned int* BbS = Bsm + bufc * (B_STG_BYTES / 4);

        MMA_SUB(AbS, BbS);                               // sub 0

        if (s + 2 < NSTG) PRODUCE(bufp, (s + 2) * KSTG); // overlaps sub1 MMAs
        else CP_COMMIT();                 // keep group accounting uniform

        MMA_SUB(AbS + A_STG_BYTES / 8, BbS + B_STG_BYTES / 8);  // sub 1

        bufc = (bufc == NSTAGE - 1) ? 0 : bufc + 1;
        bufp = (bufp == NSTAGE - 1) ? 0 : bufp + 1;
    }

    // -------- epilogue --------
    if (FFN1) {
        // packed g_H quads: idx = (wp>>3)*64 + g*8 + (wp&7), wp = n>>1
        #pragma unroll
        for (int i = 0; i < 4; i++) {
            const size_t grpglb = (size_t)((hbase + wm + i * 16) >> 4);
            float4* grow = (float4*)(g_H + grpglb * (16 * HDIM));
            #pragma unroll
            for (int j = 0; j < 8; j++) {
                const int n = n0 + wn + j * 8 + tg * 2;
                const int wp = n >> 1;
                float4 v;
                v.x = rna_tf32(gelu_tanh(acc[i][j][0] + be[n]));
                v.y = rna_tf32(gelu_tanh(acc[i][j][2] + be[n]));
                v.z = rna_tf32(gelu_tanh(acc[i][j][1] + be[n + 1]));
                v.w = rna_tf32(gelu_tanh(acc[i][j][3] + be[n + 1]));
                grow[(wp >> 3) * 64 + g * 8 + (wp & 7)] = v;
            }
        }
    } else {
        #pragma unroll
        for (int i = 0; i < 4; i++) {
            #pragma unroll
            for (int half = 0; half < 2; half++) {
                const int r = wm + i * 16 + g + half * 8;
                if (r < valid) {
                    const int tok = tok_s[r];
                    const float w = wt_s[r];
                    float* orow = outp + (size_t)tok * CDIM;
                    #pragma unroll
                    for (int j = 0; j < 8; j++) {
                        const int n = n0 + wn + j * 8 + tg * 2;
                        atomicAdd(orow + n,     w * (acc[i][j][half * 2 + 0] + be[n]));
                        atomicAdd(orow + n + 1, w * (acc[i][j][half * 2 + 1] + be[n + 1]));
                    }
                }
            }
        }
    }
    #undef PRODUCE
    #undef MMA_SUB
}

// ---------------- launch ----------------
extern "C" void kernel_launch(void* const* d_in, const int* in_sizes, int n_in,
                              void* d_out, int out_size) {
    const float* x  = (const float*)d_in[0];
    const float* gw = (const float*)d_in[1];
    const float* w1 = (const float*)d_in[2];
    const float* b1 = (const float*)d_in[3];
    const float* w2 = (const float*)d_in[4];
    const float* b2 = (const float*)d_in[5];
    float* out = (float*)d_out;

    cudaFuncSetAttribute(ffn_gemm<CDIM, true >, cudaFuncAttributeMaxDynamicSharedMemorySize, FFN_SMEM);
    cudaFuncSetAttribute(ffn_gemm<HDIM, false>, cudaFuncAttributeMaxDynamicSharedMemorySize, FFN_SMEM);

    cudaMemsetAsync(out, 0, (size_t)T_TOK * CDIM * sizeof(float));          // launch 0
    convw_all<<<2 * (NEXP * HDIM * CDIM) / 1024, 256>>>(w1, w2);            // launch 1
    router_kernel<<<T_TOK, 256>>>(x, gw);                                   // launch 2
    gather_kernel<<<MAXTILES * 8, 256>>>(x);                                // launch 3
    ffn_gemm<CDIM, true ><<<dim3(MAXTILES, HDIM / TNB), 128, FFN_SMEM>>>(b1, nullptr); // 4 (ncu)
    // FFN2: n-tile FAST (x), m-tile slow (y) -> wave-wide L2 reuse of g_H
    ffn_gemm<HDIM, false><<<dim3(CDIM / TNB, MAXTILES), 128, FFN_SMEM>>>(b2, out);     // 5
}

// round 16
// speedup vs baseline: 1.0021x; 1.0021x over previous
#include <cuda_runtime.h>
#include <math.h>
#include <stdint.h>

#define T_TOK 8192
#define CDIM  1024
#define HDIM  4096
#define NEXP  8
#define TM    128
#define TNB   128                            // CTA tile N
#define MAXTILES 136
#define HROWS_MAX (MAXTILES * TM)
#define NSTAGE 3
#define KSTG   32
#define A_STG_BYTES (TM * KSTG * 4)          // 16384 (two 8KB k16 sub-buffers)
#define B_STG_BYTES (TNB * KSTG * 4)         // 16384
#define CONVB ((2 * NEXP * HDIM * CDIM) / 1024)   // 65536 convw blocks

// ---------------- device scratch ----------------
__device__ int   g_cnt[NEXP];
__device__ int   g_done;
__device__ int   g_off[NEXP];
__device__ int   g_tok[NEXP * T_TOK];
__device__ float g_wt [NEXP * T_TOK];
__device__ int   g_tile_e[MAXTILES];
__device__ int   g_tile_l[MAXTILES];
__device__ int   g_ntiles;
// A-side buffers PACKED per 16-row group, k16-block major:
//   quad(p, wp) = {A[r][2wp], A[r+8][2wp], A[r][2wp+1], A[r+8][2wp+1]}, r = grp*16+p
//   quad index  = (wp>>3)*64 + p*8 + (wp&7)   (float offset = idx*4)
__device__ float g_X[(size_t)HROWS_MAX * CDIM];      // gathered x, packed, tf32-rounded
__device__ float g_H[(size_t)HROWS_MAX * HDIM];      // activations, packed, tf32-rounded
__device__ float g_W1[(size_t)NEXP * HDIM * CDIM];   // tf32-rounded weights (linear)
__device__ float g_W2[(size_t)NEXP * CDIM * HDIM];

// ---------------- helpers ----------------
__device__ __forceinline__ unsigned int f2tf32(float f) {
    unsigned int r;
    asm("cvt.rna.tf32.f32 %0, %1;" : "=r"(r) : "f"(f));
    return r;
}
__device__ __forceinline__ float rna_tf32(float f) { return __uint_as_float(f2tf32(f)); }

__device__ __forceinline__ uint32_t smem_u32(const void* p) {
    uint32_t a;
    asm("{ .reg .u64 t; cvta.to.shared.u64 t, %1; cvt.u32.u64 %0, t; }" : "=r"(a) : "l"(p));
    return a;
}
__device__ __forceinline__ void cpasync16(uint32_t dst, const float* src) {
    asm volatile("cp.async.cg.shared.global [%0], [%1], 16;" :: "r"(dst), "l"(src));
}
#define CP_COMMIT()  asm volatile("cp.async.commit_group;" ::: "memory")
#define CP_WAIT(n)   asm volatile("cp.async.wait_group %0;" :: "n"(n) : "memory")

__device__ __forceinline__ void mma_tf32(float c[4], unsigned int a0, unsigned int a1,
                                         unsigned int a2, unsigned int a3,
                                         unsigned int b0, unsigned int b1) {
    asm volatile(
        "mma.sync.aligned.m16n8k8.row.col.f32.tf32.tf32.f32 "
        "{%0,%1,%2,%3}, {%4,%5,%6,%7}, {%8,%9}, {%0,%1,%2,%3};"
        : "+f"(c[0]), "+f"(c[1]), "+f"(c[2]), "+f"(c[3])
        : "r"(a0), "r"(a1), "r"(a2), "r"(a3), "r"(b0), "r"(b1));
}

__device__ __forceinline__ float gelu_tanh(float v) {
    float u = v + 0.044715f * v * v * v;
    return 0.5f * v * (1.0f + tanhf(0.7978845608028654f * u));
}

// ---------------- fused weight conversion + router (+ scheduler) ----------------
// Blocks [0, CONVB): rna-round w1/w2 into g_W1/g_W2 (DRAM-bound).
// Blocks [CONVB, CONVB+T_TOK): router (rides inside convw's memory time).
// Counters g_cnt/g_done are zeroed by host-side memsets before this launch.
__global__ void conv_router_kernel(const float* __restrict__ w1,
                                   const float* __restrict__ w2,
                                   const float* __restrict__ x,
                                   const float* __restrict__ gw) {
    if (blockIdx.x < CONVB) {
        const size_t half = (size_t)(NEXP * HDIM * CDIM) / 4;   // float4 per weight
        size_t i = (size_t)blockIdx.x * 256 + threadIdx.x;
        const float4* src;
        float4* dst;
        if (i < half) { src = (const float4*)w1; dst = (float4*)g_W1; }
        else          { src = (const float4*)w2; dst = (float4*)g_W2; i -= half; }
        float4 v = src[i];
        v.x = rna_tf32(v.x); v.y = rna_tf32(v.y); v.z = rna_tf32(v.z); v.w = rna_tf32(v.w);
        dst[i] = v;
        return;
    }

    // ---- router part ----
    __shared__ float xs[CDIM];
    __shared__ float lg[NEXP];
    const int t = blockIdx.x - CONVB, tid = threadIdx.x;
    ((float4*)xs)[tid] = ((const float4*)(x + (size_t)t * CDIM))[tid];
    __syncthreads();
    const int e = tid >> 5, lane = tid & 31;
    const float* w = gw + e * CDIM;
    float s = 0.f;
    for (int i = lane * 4; i < CDIM; i += 128) {
        float4 a = *(const float4*)(xs + i);
        float4 b = *(const float4*)(w + i);
        s += a.x * b.x + a.y * b.y + a.z * b.z + a.w * b.w;
    }
    #pragma unroll
    for (int o = 16; o; o >>= 1) s += __shfl_xor_sync(0xffffffffu, s, o);
    if (lane == 0) lg[e] = s;
    __syncthreads();
    if (tid == 0) {
        float m = lg[0];
        #pragma unroll
        for (int i = 1; i < NEXP; i++) m = fmaxf(m, lg[i]);
        float p[NEXP]; float S = 0.f;
        #pragma unroll
        for (int i = 0; i < NEXP; i++) { p[i] = expf(lg[i] - m); S += p[i]; }
        #pragma unroll
        for (int i = 0; i < NEXP; i++) p[i] /= S;
        int i1 = 0;
        #pragma unroll
        for (int i = 1; i < NEXP; i++) if (p[i] > p[i1]) i1 = i;
        int i2 = (i1 == 0) ? 1 : 0;
        #pragma unroll
        for (int i = 0; i < NEXP; i++) { if (i == i1) continue; if (p[i] > p[i2]) i2 = i; }
        float denom = p[i1] + p[i2] + 1e-8f;
        float wa = p[i1] / denom, wb = p[i2] / denom;
        int pos = atomicAdd(&g_cnt[i1], 1);
        g_tok[i1 * T_TOK + pos] = t; g_wt[i1 * T_TOK + pos] = wa;
        pos = atomicAdd(&g_cnt[i2], 1);
        g_tok[i2 * T_TOK + pos] = t; g_wt[i2 * T_TOK + pos] = wb;

        __threadfence();
        int old = atomicAdd(&g_done, 1);
        if (old == T_TOK - 1) {            // last router block: build tile map
            int acc = 0, nt = 0;
            for (int ee = 0; ee < NEXP; ee++) {
                g_off[ee] = acc;
                int c = g_cnt[ee];
                int k = (c + TM - 1) / TM;
                for (int i = 0; i < k; i++) { g_tile_e[nt] = ee; g_tile_l[nt] = i; nt++; }
                acc += k * TM;
            }
            g_ntiles = nt;
            __threadfence();
        }
    }
}

// gather + rna-round x rows into PACKED per-expert segments (zero padding).
__global__ void gather_kernel(const float* __restrict__ x) {
    const int grp  = blockIdx.x;
    const int tile = grp >> 3;
    if (tile >= g_ntiles) return;
    const int e    = g_tile_e[tile];
    const int cnt  = g_cnt[e];
    const int t    = threadIdx.x;
    const int p    = t >> 5, c = t & 31;
    const int lr0  = g_tile_l[tile] * TM + (grp & 7) * 16 + p;
    const int lr8  = lr0 + 8;
    const float* s0 = (lr0 < cnt) ? x + (size_t)g_tok[e * T_TOK + lr0] * CDIM : nullptr;
    const float* s8 = (lr8 < cnt) ? x + (size_t)g_tok[e * T_TOK + lr8] * CDIM : nullptr;
    float4* dst = (float4*)(g_X + (size_t)grp * 16 * CDIM);
    #pragma unroll
    for (int j = 0; j < CDIM / 64; j++) {      // 16 iters
        const int wp = c + 32 * j;
        float2 a = s0 ? *(const float2*)(s0 + 2 * wp) : make_float2(0.f, 0.f);
        float2 b = s8 ? *(const float2*)(s8 + 2 * wp) : make_float2(0.f, 0.f);
        float4 v;
        v.x = rna_tf32(a.x); v.y = rna_tf32(b.x);
        v.z = rna_tf32(a.y); v.w = rna_tf32(b.y);
        dst[((c >> 3) + 4 * j) * 64 + p * 8 + (c & 7)] = v;
    }
}

// ---------------- grouped GEMM, mma.sync tf32, cp.async pipeline ----------------
// CTA tile 128x128, 4 warps as 2(m) x 2(n), warp tile 64x64. 2 CTAs/SM.
// Packed-A (one LDS.128 = one in-order HMMA quad). Full-XOR smem swizzle.
// Pipeline: wait(1) -> sync -> MMA(sub0) -> PRODUCE -> MMA(sub1).
// FFN2 epilogue uses vector float2 atomicAdd (sm_90+): halves RED count.
#define FFN_SMEM (1024 + NSTAGE * (A_STG_BYTES + B_STG_BYTES))

template <int KDIM, bool FFN1>
__global__ void __launch_bounds__(128, 2) ffn_gemm(const float* __restrict__ bias,
                                                   float* __restrict__ outp) {
    extern __shared__ char smem[];
    const int tile = FFN1 ? blockIdx.x : blockIdx.y;
    const int nblk = FFN1 ? blockIdx.y : blockIdx.x;
    if (tile >= g_ntiles) return;

    const float* Aglb = FFN1 ? g_X  : g_H;    // packed A (device-side symbol refs)
    const float* Bglb = FFN1 ? g_W1 : g_W2;

    const int e     = g_tile_e[tile];
    const int l     = g_tile_l[tile];
    const int cnt   = g_cnt[e];
    const int r0    = l * TM;
    const int valid = min(TM, cnt - r0);
    const int NB    = FFN1 ? HDIM : CDIM;
    const int n0    = nblk * TNB;
    const float* Bexp = Bglb + (size_t)e * KDIM * NB;
    const float* be   = bias + e * NB;
    const int hbase   = g_off[e] + r0;        // multiple of 128
    const int tid = threadIdx.x, wid = tid >> 5, lane = tid & 31;

    int*   tok_s = (int*)smem;
    float* wt_s  = (float*)(smem + 512);
    unsigned int* Asm = (unsigned int*)(smem + 1024);
    unsigned int* Bsm = (unsigned int*)(smem + 1024 + NSTAGE * A_STG_BYTES);
    const uint32_t Abase_u = smem_u32(Asm);
    const uint32_t Bbase_u = smem_u32(Bsm);

    {   // all 128 threads load token map
        bool v = tid < valid;
        int idx = e * T_TOK + r0 + tid;
        tok_s[tid] = v ? g_tok[idx] : 0;
        wt_s[tid]  = v ? g_wt[idx]  : 0.f;
    }
    __syncthreads();

    // cp.async mapping for one 32-k stage (A chunk c: q fast -> coalesced src):
    const float* aS[8]; uint32_t aD[8];
    const float* bS[8]; uint32_t bD[8];
    #pragma unroll
    for (int i = 0; i < 8; i++) {
        const int c = tid + 128 * i;
        const int q = c & 7, p = (c >> 3) & 7, grp = (c >> 6) & 7, sub = c >> 9;
        aS[i] = Aglb + ((size_t)((hbase >> 4) + grp)) * (16 * KDIM) + sub * 256 + p * 32 + q * 4;
        aD[i] = Abase_u + sub * (A_STG_BYTES / 2) + grp * 1024 + (p * 8 + (q ^ p)) * 16;
        const int row = c >> 3, cw = c & 7;
        bS[i] = Bexp + (size_t)(n0 + row) * KDIM + cw * 4;
        bD[i] = Bbase_u + (cw >> 2) * (B_STG_BYTES / 2) + row * 64 + (cw & 3) * 16;
    }

    #define PRODUCE(bufi, kof) do { \
        const uint32_t _oa = (bufi) * A_STG_BYTES; \
        const uint32_t _ob = (bufi) * B_STG_BYTES; \
        _Pragma("unroll") \
        for (int _i = 0; _i < 8; _i++) cpasync16(aD[_i] + _oa, aS[_i] + ((kof) << 4)); \
        _Pragma("unroll") \
        for (int _i = 0; _i < 8; _i++) cpasync16(bD[_i] + _ob, bS[_i] + (kof)); \
        CP_COMMIT(); \
    } while (0)

    const int wm = (wid & 1) * 64;        // warp m offset (0/64)
    const int wn = (wid >> 1) * 64;       // warp n offset (0/64)
    const int g  = lane >> 2, tg = lane & 3;
    const int aoff0 = (g * 8 + ((2 * tg)     ^ g)) * 4;
    const int aoff1 = (g * 8 + ((2 * tg + 1) ^ g)) * 4;

    float acc[4][8][4];
    #pragma unroll
    for (int i = 0; i < 4; i++)
        #pragma unroll
        for (int j = 0; j < 8; j++)
            #pragma unroll
            for (int q = 0; q < 4; q++) acc[i][j][q] = 0.f;

    #define MMA_SUB(Ab, Bb) do { \
        uint4 aQ[4][2]; \
        _Pragma("unroll") \
        for (int i = 0; i < 4; i++) { \
            const int gb = ((wm >> 4) + i) * 256; \
            aQ[i][0] = *(const uint4*)((Ab) + gb + aoff0); \
            aQ[i][1] = *(const uint4*)((Ab) + gb + aoff1); \
        } \
        _Pragma("unroll") \
        for (int j = 0; j < 8; j++) { \
            const int nb = wn + j * 8 + g; \
            const uint4 bF = *(const uint4*)((Bb) + nb * 16 + tg * 4); \
            _Pragma("unroll") \
            for (int i = 0; i < 4; i++) \
                mma_tf32(acc[i][j], aQ[i][0].x, aQ[i][0].y, aQ[i][0].z, aQ[i][0].w, \
                         bF.x, bF.y); \
            _Pragma("unroll") \
            for (int i = 0; i < 4; i++) \
                mma_tf32(acc[i][j], aQ[i][1].x, aQ[i][1].y, aQ[i][1].z, aQ[i][1].w, \
                         bF.z, bF.w); \
        } \
    } while (0)

    const int NSTG = KDIM / KSTG;         // 32 (FFN1) or 128 (FFN2)
    PRODUCE(0, 0);
    PRODUCE(1, KSTG);

    int bufc = 0, bufp = 2;
    #pragma unroll 1
    for (int s = 0; s < NSTG; s++) {
        CP_WAIT(1);                       // commits = 2+s; complete >= s+1
        __syncthreads();                  // single barrier per stage

        const unsigned int* AbS = Asm + bufc * (A_STG_BYTES / 4);
        const unsigned int* BbS = Bsm + bufc * (B_STG_BYTES / 4);

        MMA_SUB(AbS, BbS);                               // sub 0

        if (s + 2 < NSTG) PRODUCE(bufp, (s + 2) * KSTG); // overlaps sub1 MMAs
        else CP_COMMIT();                 // keep group accounting uniform

        MMA_SUB(AbS + A_STG_BYTES / 8, BbS + B_STG_BYTES / 8);  // sub 1

        bufc = (bufc == NSTAGE - 1) ? 0 : bufc + 1;
        bufp = (bufp == NSTAGE - 1) ? 0 : bufp + 1;
    }

    // -------- epilogue --------
    if (FFN1) {
        // packed g_H quads: idx = (wp>>3)*64 + g*8 + (wp&7), wp = n>>1
        #pragma unroll
        for (int i = 0; i < 4; i++) {
            const size_t grpglb = (size_t)((hbase + wm + i * 16) >> 4);
            float4* grow = (float4*)(g_H + grpglb * (16 * HDIM));
            #pragma unroll
            for (int j = 0; j < 8; j++) {
                const int n = n0 + wn + j * 8 + tg * 2;
                const int wp = n >> 1;
                float4 v;
                v.x = rna_tf32(gelu_tanh(acc[i][j][0] + be[n]));
                v.y = rna_tf32(gelu_tanh(acc[i][j][2] + be[n]));
                v.z = rna_tf32(gelu_tanh(acc[i][j][1] + be[n + 1]));
                v.w = rna_tf32(gelu_tanh(acc[i][j][3] + be[n + 1]));
                grow[(wp >> 3) * 64 + g * 8 + (wp & 7)] = v;
            }
        }
    } else {
        #pragma unroll
        for (int i = 0; i < 4; i++) {
            #pragma unroll
            for (int half = 0; half < 2; half++) {
                const int r = wm + i * 16 + g + half * 8;
                if (r < valid) {
                    const int tok = tok_s[r];
                    const float w = wt_s[r];
                    float* orow = outp + (size_t)tok * CDIM;
                    #pragma unroll
                    for (int j = 0; j < 8; j++) {
                        const int n = n0 + wn + j * 8 + tg * 2;
                        float2 v;
                        v.x = w * (acc[i][j][half * 2 + 0] + be[n]);
                        v.y = w * (acc[i][j][half * 2 + 1] + be[n + 1]);
                        atomicAdd((float2*)(orow + n), v);   // RED.F32x2
                    }
                }
            }
        }
    }
    #undef PRODUCE
    #undef MMA_SUB
}

// ---------------- launch ----------------
extern "C" void kernel_launch(void* const* d_in, const int* in_sizes, int n_in,
                              void* d_out, int out_size) {
    const float* x  = (const float*)d_in[0];
    const float* gw = (const float*)d_in[1];
    const float* w1 = (const float*)d_in[2];
    const float* b1 = (const float*)d_in[3];
    const float* w2 = (const float*)d_in[4];
    const float* b2 = (const float*)d_in[5];
    float* out = (float*)d_out;

    cudaFuncSetAttribute(ffn_gemm<CDIM, true >, cudaFuncAttributeMaxDynamicSharedMemorySize, FFN_SMEM);
    cudaFuncSetAttribute(ffn_gemm<HDIM, false>, cudaFuncAttributeMaxDynamicSharedMemorySize, FFN_SMEM);

    void* p_cnt = nullptr; void* p_done = nullptr;
    cudaGetSymbolAddress(&p_cnt,  g_cnt);
    cudaGetSymbolAddress(&p_done, g_done);

    cudaMemsetAsync(out, 0, (size_t)T_TOK * CDIM * sizeof(float));
    cudaMemsetAsync(p_cnt,  0, NEXP * sizeof(int));
    cudaMemsetAsync(p_done, 0, sizeof(int));
    conv_router_kernel<<<CONVB + T_TOK, 256>>>(w1, w2, x, gw);
    gather_kernel<<<MAXTILES * 8, 256>>>(x);
    ffn_gemm<CDIM, true ><<<dim3(MAXTILES, HDIM / TNB), 128, FFN_SMEM>>>(b1, nullptr);
    // FFN2: n-tile FAST (x), m-tile slow (y)
    ffn_gemm<HDIM, false><<<dim3(CDIM / TNB, MAXTILES), 128, FFN_SMEM>>>(b2, out);
}